// round 3
// baseline (speedup 1.0000x reference)
#include <cuda_runtime.h>
#include <math.h>

// ---------------- problem constants (shapes are fixed by the dataset) -------
#define NMAX   100000
#define EMAX   3200000
#define ETOTMAX (EMAX + NMAX)
#define HC     32          // H*C
#define FIN    1433

// ---------------- scratch (device globals: allocation-free rule) ------------
__device__ __align__(128) float g_xl [NMAX * HC];
__device__ __align__(128) float g_xr [NMAX * HC];
__device__ __align__(128) float g_e  [ETOTMAX * 2];
__device__ __align__(128) float g_m  [NMAX * 2];
__device__ __align__(128) float g_s  [NMAX * 2];
__device__ __align__(128) float g_agg[NMAX * HC];
__device__ __align__(128) float g_h  [NMAX * HC];
__device__ __align__(128) int   g_src[ETOTMAX];
__device__ __align__(128) int   g_dst[ETOTMAX];
__device__ int g_i32flag;   // 1 if edge_index delivered as int32, 0 if int64

// ---------------- small PTX helpers -----------------------------------------
__device__ __forceinline__ unsigned long long dup2(float v) {
    unsigned long long r;
    asm("mov.b64 %0, {%1, %1};" : "=l"(r) : "f"(v));
    return r;
}
__device__ __forceinline__ float2 unpack2(unsigned long long v) {
    float2 r;
    asm("mov.b64 {%0, %1}, %2;" : "=f"(r.x), "=f"(r.y) : "l"(v));
    return r;
}
#define FMA2(d, a, b) asm("fma.rn.f32x2 %0, %1, %2, %0;" : "+l"(d) : "l"(a), "l"(b))

__device__ __forceinline__ void red2(float* p, float a, float b) {
    asm volatile("red.global.add.v2.f32 [%0], {%1, %2};" :: "l"(p), "f"(a), "f"(b) : "memory");
}
__device__ __forceinline__ void red4(float* p, float a, float b, float c, float d) {
    asm volatile("red.global.add.v4.f32 [%0], {%1, %2, %3, %4};"
                 :: "l"(p), "f"(a), "f"(b), "f"(c), "f"(d) : "memory");
}
__device__ __forceinline__ void atomMaxF(float* a, float v) {
    if (v >= 0.0f) atomicMax((int*)a, __float_as_int(v));
    else           atomicMin((unsigned int*)a, __float_as_uint(v));
}

// ---------------- kernels -1/-2: detect edge_index dtype --------------------
// If data is int64 (values < 2^31), every odd int32 word in the first E
// logical elements is zero. If int32, odd words are random node ids.
__global__ void k_flag0() { if (threadIdx.x == 0 && blockIdx.x == 0) g_i32flag = 0; }

__global__ void k_detect(const int* __restrict__ w, int E) {
    // inspect first 2*E int32 words (== first E int64 elements under the
    // int64 interpretation; safe to read under both interpretations)
    long long i = (long long)blockIdx.x * blockDim.x + threadIdx.x;
    long long nwords = (long long)E;           // number of ODD positions checked
    if (i >= nwords) return;
    int v = w[2 * i + 1];
    if (v != 0) g_i32flag = 1;                 // benign race: all writers write 1
}

// ---------------- kernel 0: edge index prep (+ self loops, clamp) -----------
__global__ void k_prep(const void* __restrict__ eiv, int E, int n) {
    int i = blockIdx.x * blockDim.x + threadIdx.x;
    int etot = E + n;
    if (i >= etot) return;
    int s, d;
    if (i < E) {
        if (g_i32flag) {
            const int* ei = (const int*)eiv;
            s = ei[i];
            d = ei[(size_t)E + i];
        } else {
            const long long* ei = (const long long*)eiv;
            s = (int)ei[i];
            d = (int)ei[(size_t)E + i];
        }
        // clamp: turn any decode error into a wrong answer, never an IMA
        s = min(max(s, 0), n - 1);
        d = min(max(d, 0), n - 1);
    } else {
        s = i - E;
        d = i - E;
    }
    g_src[i] = s;
    g_dst[i] = d;
}

// ---------------- kernel 1: big fused GEMM  x @ [Wl | Wr] -> xl, xr ---------
// BM=128, BN=64(all cols), BK=16, 256 threads, f32x2 packed FMA.
__global__ __launch_bounds__(256) void k_gemm1(
    const float* __restrict__ x, const float* __restrict__ Wl,
    const float* __restrict__ Wr, int n, int K)
{
    __shared__ float Xs[16][128];   // [k][row]
    __shared__ float Ws[16][64];    // [k][col]

    const int tid = threadIdx.x;
    const int tx = tid & 15, ty = tid >> 4;
    const int row0 = blockIdx.x * 128;
    const int my_r = ty * 8;        // 8 rows per thread
    const int my_c = tx * 4;        // 4 cols per thread

    unsigned long long acc[4][4];
#pragma unroll
    for (int i = 0; i < 4; i++)
#pragma unroll
        for (int j = 0; j < 4; j++) acc[i][j] = 0ull;

    // W-load addressing (fixed across chunks)
    const int wk = tid >> 4;        // 0..15
    const int wc4 = tid & 15;       // 0..15 -> 4 cols
    const float* wsrc = (wc4 < 8) ? Wl : Wr;
    const int wcc = (wc4 < 8) ? wc4 * 4 : (wc4 - 8) * 4;

    for (int k0 = 0; k0 < K; k0 += 16) {
        // --- load X tile: 128 rows x 16 k, scalar (rows are not 16B aligned)
#pragma unroll
        for (int l = 0; l < 2; l++) {
            int id = tid + l * 256;          // 0..511
            int r  = id >> 2;                // 0..127
            int kq = (id & 3) * 4;           // 0,4,8,12
            int gr = row0 + r; if (gr >= n) gr = n - 1;
            const float* xp = x + (size_t)gr * K + (k0 + kq);
#pragma unroll
            for (int q = 0; q < 4; q++) {
                float v = (k0 + kq + q < K) ? xp[q] : 0.0f;
                Xs[kq + q][r] = v;
            }
        }
        // --- load W tile
        {
            int gk = k0 + wk;
            float4 wv = make_float4(0.f, 0.f, 0.f, 0.f);
            if (gk < K) wv = *(const float4*)(wsrc + (size_t)gk * HC + wcc);
            *(float4*)&Ws[wk][wc4 * 4] = wv;
        }
        __syncthreads();

#pragma unroll
        for (int kk = 0; kk < 16; kk++) {
            ulonglong2 xa = *(const ulonglong2*)&Xs[kk][my_r];
            ulonglong2 xb = *(const ulonglong2*)&Xs[kk][my_r + 4];
            float4 wv = *(const float4*)&Ws[kk][my_c];
            unsigned long long w0 = dup2(wv.x), w1 = dup2(wv.y);
            unsigned long long w2 = dup2(wv.z), w3 = dup2(wv.w);
            FMA2(acc[0][0], xa.x, w0); FMA2(acc[0][1], xa.x, w1);
            FMA2(acc[0][2], xa.x, w2); FMA2(acc[0][3], xa.x, w3);
            FMA2(acc[1][0], xa.y, w0); FMA2(acc[1][1], xa.y, w1);
            FMA2(acc[1][2], xa.y, w2); FMA2(acc[1][3], xa.y, w3);
            FMA2(acc[2][0], xb.x, w0); FMA2(acc[2][1], xb.x, w1);
            FMA2(acc[2][2], xb.x, w2); FMA2(acc[2][3], xb.x, w3);
            FMA2(acc[3][0], xb.y, w0); FMA2(acc[3][1], xb.y, w1);
            FMA2(acc[3][2], xb.y, w2); FMA2(acc[3][3], xb.y, w3);
        }
        __syncthreads();
    }

    // --- store
    float* base = (my_c < HC) ? g_xl : g_xr;
    int cc = my_c & (HC - 1);
#pragma unroll
    for (int rp = 0; rp < 4; rp++) {
        float2 p0 = unpack2(acc[rp][0]);
        float2 p1 = unpack2(acc[rp][1]);
        float2 p2 = unpack2(acc[rp][2]);
        float2 p3 = unpack2(acc[rp][3]);
        int r_even = row0 + my_r + rp * 2;
        if (r_even < n)
            *(float4*)&base[(size_t)r_even * HC + cc] = make_float4(p0.x, p1.x, p2.x, p3.x);
        int r_odd = r_even + 1;
        if (r_odd < n)
            *(float4*)&base[(size_t)r_odd * HC + cc] = make_float4(p0.y, p1.y, p2.y, p3.y);
    }
}

// ---------------- kernel 2: init m=-inf, s=0, agg=0 -------------------------
__global__ void k_init(int n) {
    int i = blockIdx.x * blockDim.x + threadIdx.x;
    if (i < n * HC) g_agg[i] = 0.0f;
    if (i < n * 2) { g_m[i] = __int_as_float(0xff800000); g_s[i] = 0.0f; }
}

// ---------------- kernel 3: per-edge scores + segment max -------------------
__global__ __launch_bounds__(256) void k_score(const float* __restrict__ att, int etot) {
    int i = blockIdx.x * blockDim.x + threadIdx.x;
    if (i >= etot) return;
    int s = g_src[i], d = g_dst[i];
    const float4* pl = (const float4*)(g_xl + (size_t)s * HC);
    const float4* pr = (const float4*)(g_xr + (size_t)d * HC);
#pragma unroll
    for (int h = 0; h < 2; h++) {
        float acc = 0.0f;
#pragma unroll
        for (int g = 0; g < 4; g++) {
            float4 a = pl[h * 4 + g];
            float4 b = pr[h * 4 + g];
            const float* ap = att + h * 16 + g * 4;
            float z;
            z = a.x + b.x; z = fmaxf(z, 0.2f * z); acc += z * ap[0];
            z = a.y + b.y; z = fmaxf(z, 0.2f * z); acc += z * ap[1];
            z = a.z + b.z; z = fmaxf(z, 0.2f * z); acc += z * ap[2];
            z = a.w + b.w; z = fmaxf(z, 0.2f * z); acc += z * ap[3];
        }
        g_e[(size_t)i * 2 + h] = acc;
        atomMaxF(&g_m[d * 2 + h], acc);
    }
}

// ---------------- kernel 4: exp, segment sum, weighted aggregation ----------
__global__ __launch_bounds__(256) void k_aggregate(int etot) {
    int i = blockIdx.x * blockDim.x + threadIdx.x;
    if (i >= etot) return;
    int s = g_src[i], d = g_dst[i];
    float2 ev = *(const float2*)(g_e + (size_t)i * 2);
    float2 mv = *(const float2*)(g_m + (size_t)d * 2);
    float ex0 = __expf(ev.x - mv.x);
    float ex1 = __expf(ev.y - mv.y);
    red2(&g_s[d * 2], ex0, ex1);
    const float4* pl = (const float4*)(g_xl + (size_t)s * HC);
    float* out = g_agg + (size_t)d * HC;
#pragma unroll
    for (int g = 0; g < 8; g++) {
        float sc = (g < 4) ? ex0 : ex1;
        float4 v = pl[g];
        red4(out + g * 4, v.x * sc, v.y * sc, v.z * sc, v.w * sc);
    }
}

// ---------------- kernel 5: node finalize layer 1 (normalize + bias + elu) --
__global__ void k_final1(const float* __restrict__ bias, int n) {
    int i = blockIdx.x * blockDim.x + threadIdx.x;
    if (i >= n * HC) return;
    int node = i >> 5, c = i & 31, h = c >> 4;
    float v = g_agg[i] / (g_s[node * 2 + h] + 1e-16f) + bias[c];
    g_h[i] = (v > 0.0f) ? v : expm1f(v);
}

// ---------------- kernel 6: small GEMM  h @ [Wl2 | Wr2] (K=32) --------------
__global__ __launch_bounds__(256) void k_gemm2(
    const float* __restrict__ Wl, const float* __restrict__ Wr, int n)
{
    __shared__ float Ws[32 * 64];   // [k][col]
    __shared__ float hs[4][32];
    int tid = threadIdx.x;
#pragma unroll
    for (int l = 0; l < 8; l++) {
        int id = tid + l * 256;
        int k = id >> 6, c = id & 63;
        Ws[id] = (c < HC) ? Wl[k * HC + c] : Wr[k * HC + (c - HC)];
    }
    int node0 = blockIdx.x * 4;
    if (tid < 128) {
        int nn = node0 + (tid >> 5), k = tid & 31;
        hs[tid >> 5][k] = (nn < n) ? g_h[(size_t)nn * HC + k] : 0.0f;
    }
    __syncthreads();
    int ln = tid >> 6, c = tid & 63;
    int node = node0 + ln;
    if (node >= n) return;
    float acc = 0.0f;
#pragma unroll
    for (int k = 0; k < 32; k++) acc += hs[ln][k] * Ws[k * 64 + c];
    if (c < HC) g_xl[(size_t)node * HC + c] = acc;
    else        g_xr[(size_t)node * HC + (c - HC)] = acc;
}

// ---------------- kernel 7: finalize layer 2 + FC + log_softmax -> out ------
__global__ void k_final2(const float* __restrict__ bias,
                         const float* __restrict__ fcW,
                         const float* __restrict__ fcb,
                         float* __restrict__ out, int n)
{
    int node = blockIdx.x * blockDim.x + threadIdx.x;
    if (node >= n) return;
    float s0 = g_s[node * 2 + 0] + 1e-16f;
    float s1 = g_s[node * 2 + 1] + 1e-16f;
    const float4* ag = (const float4*)(g_agg + (size_t)node * HC);
    float h2[32];
#pragma unroll
    for (int g = 0; g < 8; g++) {
        float4 v = ag[g];
        float inv = 1.0f / ((g < 4) ? s0 : s1);
        int c = g * 4;
        float t;
        t = v.x * inv + bias[c + 0]; h2[c + 0] = (t > 0.f) ? t : expm1f(t);
        t = v.y * inv + bias[c + 1]; h2[c + 1] = (t > 0.f) ? t : expm1f(t);
        t = v.z * inv + bias[c + 2]; h2[c + 2] = (t > 0.f) ? t : expm1f(t);
        t = v.w * inv + bias[c + 3]; h2[c + 3] = (t > 0.f) ? t : expm1f(t);
    }
    float lg[7];
#pragma unroll
    for (int j = 0; j < 7; j++) lg[j] = fcb[j];
#pragma unroll
    for (int k = 0; k < 32; k++) {
        float hv = h2[k];
#pragma unroll
        for (int j = 0; j < 7; j++) lg[j] += hv * fcW[k * 7 + j];
    }
    float mx = lg[0];
#pragma unroll
    for (int j = 1; j < 7; j++) mx = fmaxf(mx, lg[j]);
    float ssum = 0.0f;
#pragma unroll
    for (int j = 0; j < 7; j++) ssum += expf(lg[j] - mx);
    float lse = mx + logf(ssum);
#pragma unroll
    for (int j = 0; j < 7; j++) out[(size_t)node * 7 + j] = lg[j] - lse;
}

// ---------------- launch -----------------------------------------------------
extern "C" void kernel_launch(void* const* d_in, const int* in_sizes, int n_in,
                              void* d_out, int out_size)
{
    const float* x    = (const float*)d_in[0];
    const void*  ei   = d_in[1];
    const float* Wl1  = (const float*)d_in[2];
    const float* Wr1  = (const float*)d_in[3];
    const float* a1   = (const float*)d_in[4];
    const float* b1   = (const float*)d_in[5];
    const float* Wl2  = (const float*)d_in[6];
    const float* Wr2  = (const float*)d_in[7];
    const float* a2   = (const float*)d_in[8];
    const float* b2   = (const float*)d_in[9];
    const float* fcW  = (const float*)d_in[10];
    const float* fcb  = (const float*)d_in[11];
    float*       out  = (float*)d_out;

    const int K = in_sizes[2] / HC;          // 1433
    const int n = in_sizes[0] / K;           // 100000
    const int E = in_sizes[1] / 2;           // 3200000
    const int etot = E + n;

    const int TB = 256;
    dim3 gEdge((etot + TB - 1) / TB);
    dim3 gNC((n * HC + TB - 1) / TB);

    // --- decode edge_index dtype (int32 vs int64), then prep indices
    k_flag0<<<1, 32>>>();
    k_detect<<<(E + TB - 1) / TB, TB>>>((const int*)ei, E);
    k_prep<<<gEdge, TB>>>(ei, E, n);

    k_gemm1<<<(n + 127) / 128, 256>>>(x, Wl1, Wr1, n, K);

    // ---- layer 1 attention
    k_init<<<gNC, TB>>>(n);
    k_score<<<gEdge, TB>>>(a1, etot);
    k_aggregate<<<gEdge, TB>>>(etot);
    k_final1<<<gNC, TB>>>(b1, n);

    // ---- layer 2
    k_gemm2<<<(n + 3) / 4, 256>>>(Wl2, Wr2, n);
    k_init<<<gNC, TB>>>(n);
    k_score<<<gEdge, TB>>>(a2, etot);
    k_aggregate<<<gEdge, TB>>>(etot);
    k_final2<<<(n + TB - 1) / TB, TB>>>(b2, fcW, fcb, out, n);
}

// round 4
// speedup vs baseline: 1.5665x; 1.5665x over previous
#include <cuda_runtime.h>
#include <math.h>

// ---------------- problem constants ------------------------------------------
#define NMAX   100000
#define EMAX   3200000
#define ETOTMAX (EMAX + NMAX)
#define HC     32          // H*C

// ---------------- scratch (device globals: allocation-free rule) -------------
__device__ __align__(128) float g_xl [NMAX * HC];
__device__ __align__(128) float g_xr [NMAX * HC];
__device__ __align__(128) float g_h  [NMAX * HC];
__device__ __align__(128) int   g_src[ETOTMAX];
__device__ __align__(128) int   g_dst[ETOTMAX];
__device__ __align__(128) int   g_csrc[ETOTMAX];   // CSR: src ids sorted by dst
__device__ __align__(128) int   g_cnt[NMAX];
__device__ __align__(128) int   g_rp [NMAX + 1];   // CSR row pointers
__device__ __align__(128) int   g_pos[NMAX];       // scatter cursors
__device__ int g_i32flag;   // 1 if edge_index delivered as int32, 0 if int64

// ---------------- small PTX helpers ------------------------------------------
__device__ __forceinline__ unsigned long long dup2(float v) {
    unsigned long long r;
    asm("mov.b64 %0, {%1, %1};" : "=l"(r) : "f"(v));
    return r;
}
__device__ __forceinline__ float2 unpack2(unsigned long long v) {
    float2 r;
    asm("mov.b64 {%0, %1}, %2;" : "=f"(r.x), "=f"(r.y) : "l"(v));
    return r;
}
#define FMA2(d, a, b) asm("fma.rn.f32x2 %0, %1, %2, %0;" : "+l"(d) : "l"(a), "l"(b))

// ---------------- dtype detect (int32 vs int64 edge_index) -------------------
__global__ void k_flag0() { if (threadIdx.x == 0 && blockIdx.x == 0) g_i32flag = 0; }

__global__ void k_detect(const int* __restrict__ w, int E) {
    long long i = (long long)blockIdx.x * blockDim.x + threadIdx.x;
    if (i >= E) return;
    if (w[2 * i + 1] != 0) g_i32flag = 1;     // benign race
}

// ---------------- edge decode (+ self loops, clamp) ---------------------------
__global__ void k_prep(const void* __restrict__ eiv, int E, int n) {
    int i = blockIdx.x * blockDim.x + threadIdx.x;
    int etot = E + n;
    if (i >= etot) return;
    int s, d;
    if (i < E) {
        if (g_i32flag) {
            const int* ei = (const int*)eiv;
            s = ei[i]; d = ei[(size_t)E + i];
        } else {
            const long long* ei = (const long long*)eiv;
            s = (int)ei[i]; d = (int)ei[(size_t)E + i];
        }
        s = min(max(s, 0), n - 1);
        d = min(max(d, 0), n - 1);
    } else {
        s = i - E; d = i - E;
    }
    g_src[i] = s;
    g_dst[i] = d;
}

// ---------------- counting sort by dst ----------------------------------------
__global__ void k_zero(int n) {
    int i = blockIdx.x * blockDim.x + threadIdx.x;
    if (i < n) g_cnt[i] = 0;
}
__global__ void k_hist(int etot) {
    int i = blockIdx.x * blockDim.x + threadIdx.x;
    if (i < etot) atomicAdd(&g_cnt[g_dst[i]], 1);
}
__device__ __align__(128) int g_blk[128];
__global__ __launch_bounds__(1024) void k_scan1(int n) {
    __shared__ int sh[1024];
    int i = blockIdx.x * 1024 + threadIdx.x;
    int v = (i < n) ? g_cnt[i] : 0;
    sh[threadIdx.x] = v;
    __syncthreads();
#pragma unroll
    for (int o = 1; o < 1024; o <<= 1) {
        int t = (threadIdx.x >= o) ? sh[threadIdx.x - o] : 0;
        __syncthreads();
        sh[threadIdx.x] += t;
        __syncthreads();
    }
    if (i < n) g_rp[i] = sh[threadIdx.x] - v;   // exclusive
    if (threadIdx.x == 1023) g_blk[blockIdx.x] = sh[1023];
}
__global__ void k_scan2(int nb) {
    if (threadIdx.x == 0 && blockIdx.x == 0) {
        int run = 0;
        for (int b = 0; b < nb; b++) { int t = g_blk[b]; g_blk[b] = run; run += t; }
    }
}
__global__ void k_scan3(int n, int etot) {
    int i = blockIdx.x * blockDim.x + threadIdx.x;
    if (i < n) {
        int v = g_rp[i] + g_blk[i >> 10];
        g_rp[i] = v;
        g_pos[i] = v;
    }
    if (i == 0) g_rp[n] = etot;
}
__global__ void k_scatter(int etot) {
    int i = blockIdx.x * blockDim.x + threadIdx.x;
    if (i >= etot) return;
    int p = atomicAdd(&g_pos[g_dst[i]], 1);
    g_csrc[p] = g_src[i];
}

// ---------------- kernel: big fused GEMM  x @ [Wl | Wr] -> xl, xr -------------
__global__ __launch_bounds__(256) void k_gemm1(
    const float* __restrict__ x, const float* __restrict__ Wl,
    const float* __restrict__ Wr, int n, int K)
{
    __shared__ float Xs[16][128];
    __shared__ float Ws[16][64];

    const int tid = threadIdx.x;
    const int tx = tid & 15, ty = tid >> 4;
    const int row0 = blockIdx.x * 128;
    const int my_r = ty * 8;
    const int my_c = tx * 4;

    unsigned long long acc[4][4];
#pragma unroll
    for (int i = 0; i < 4; i++)
#pragma unroll
        for (int j = 0; j < 4; j++) acc[i][j] = 0ull;

    const int wk = tid >> 4;
    const int wc4 = tid & 15;
    const float* wsrc = (wc4 < 8) ? Wl : Wr;
    const int wcc = (wc4 < 8) ? wc4 * 4 : (wc4 - 8) * 4;

    for (int k0 = 0; k0 < K; k0 += 16) {
#pragma unroll
        for (int l = 0; l < 2; l++) {
            int id = tid + l * 256;
            int r  = id >> 2;
            int kq = (id & 3) * 4;
            int gr = row0 + r; if (gr >= n) gr = n - 1;
            const float* xp = x + (size_t)gr * K + (k0 + kq);
#pragma unroll
            for (int q = 0; q < 4; q++) {
                float v = (k0 + kq + q < K) ? xp[q] : 0.0f;
                Xs[kq + q][r] = v;
            }
        }
        {
            int gk = k0 + wk;
            float4 wv = make_float4(0.f, 0.f, 0.f, 0.f);
            if (gk < K) wv = *(const float4*)(wsrc + (size_t)gk * HC + wcc);
            *(float4*)&Ws[wk][wc4 * 4] = wv;
        }
        __syncthreads();

#pragma unroll
        for (int kk = 0; kk < 16; kk++) {
            ulonglong2 xa = *(const ulonglong2*)&Xs[kk][my_r];
            ulonglong2 xb = *(const ulonglong2*)&Xs[kk][my_r + 4];
            float4 wv = *(const float4*)&Ws[kk][my_c];
            unsigned long long w0 = dup2(wv.x), w1 = dup2(wv.y);
            unsigned long long w2 = dup2(wv.z), w3 = dup2(wv.w);
            FMA2(acc[0][0], xa.x, w0); FMA2(acc[0][1], xa.x, w1);
            FMA2(acc[0][2], xa.x, w2); FMA2(acc[0][3], xa.x, w3);
            FMA2(acc[1][0], xa.y, w0); FMA2(acc[1][1], xa.y, w1);
            FMA2(acc[1][2], xa.y, w2); FMA2(acc[1][3], xa.y, w3);
            FMA2(acc[2][0], xb.x, w0); FMA2(acc[2][1], xb.x, w1);
            FMA2(acc[2][2], xb.x, w2); FMA2(acc[2][3], xb.x, w3);
            FMA2(acc[3][0], xb.y, w0); FMA2(acc[3][1], xb.y, w1);
            FMA2(acc[3][2], xb.y, w2); FMA2(acc[3][3], xb.y, w3);
        }
        __syncthreads();
    }

    float* base = (my_c < HC) ? g_xl : g_xr;
    int cc = my_c & (HC - 1);
#pragma unroll
    for (int rp = 0; rp < 4; rp++) {
        float2 p0 = unpack2(acc[rp][0]);
        float2 p1 = unpack2(acc[rp][1]);
        float2 p2 = unpack2(acc[rp][2]);
        float2 p3 = unpack2(acc[rp][3]);
        int r_even = row0 + my_r + rp * 2;
        if (r_even < n)
            *(float4*)&base[(size_t)r_even * HC + cc] = make_float4(p0.x, p1.x, p2.x, p3.x);
        int r_odd = r_even + 1;
        if (r_odd < n)
            *(float4*)&base[(size_t)r_odd * HC + cc] = make_float4(p0.y, p1.y, p2.y, p3.y);
    }
}

// ---------------- per-node fused attention core --------------------------------
// One warp per node. lane = channel. Returns normalized+bias value per lane.
__device__ __forceinline__ float attn_node(int node, int lane,
                                           const float* __restrict__ att,
                                           const float* __restrict__ bias)
{
    int beg = g_rp[node], end = g_rp[node + 1];
    float xr_c  = g_xr[(size_t)node * HC + lane];
    float att_c = att[lane];
    float acc = 0.0f, ssum = 0.0f;
    for (int base = beg; base < end; base += 32) {
        int idx = base + lane;
        int sl = (idx < end) ? g_csrc[idx] : 0;
        int cnt = min(32, end - base);
        for (int k = 0; k < cnt; k++) {
            int sk = __shfl_sync(0xffffffffu, sl, k);
            float xlv = __ldg(&g_xl[(size_t)sk * HC + lane]);
            float z = xlv + xr_c;
            z = fmaxf(z, 0.2f * z);
            float p = z * att_c;
            p += __shfl_xor_sync(0xffffffffu, p, 8);
            p += __shfl_xor_sync(0xffffffffu, p, 4);
            p += __shfl_xor_sync(0xffffffffu, p, 2);
            p += __shfl_xor_sync(0xffffffffu, p, 1);  // per-half-warp head sum
            float ex = __expf(p);
            ssum += ex;
            acc = fmaf(ex, xlv, acc);
        }
    }
    return acc / (ssum + 1e-16f) + bias[lane];
}

// ---------------- layer 1: attention + ELU -> g_h ------------------------------
__global__ __launch_bounds__(256) void k_attn1(const float* __restrict__ att,
                                               const float* __restrict__ bias, int n)
{
    int w = (blockIdx.x * blockDim.x + threadIdx.x) >> 5;
    int lane = threadIdx.x & 31;
    if (w >= n) return;
    float v = attn_node(w, lane, att, bias);
    g_h[(size_t)w * HC + lane] = (v > 0.0f) ? v : expm1f(v);
}

// ---------------- small GEMM  h @ [Wl2 | Wr2] (K=32) ----------------------------
__global__ __launch_bounds__(256) void k_gemm2(
    const float* __restrict__ Wl, const float* __restrict__ Wr, int n)
{
    __shared__ float Ws[32 * 64];
    __shared__ float hs[4][32];
    int tid = threadIdx.x;
#pragma unroll
    for (int l = 0; l < 8; l++) {
        int id = tid + l * 256;
        int k = id >> 6, c = id & 63;
        Ws[id] = (c < HC) ? Wl[k * HC + c] : Wr[k * HC + (c - HC)];
    }
    int node0 = blockIdx.x * 4;
    if (tid < 128) {
        int nn = node0 + (tid >> 5), k = tid & 31;
        hs[tid >> 5][k] = (nn < n) ? g_h[(size_t)nn * HC + k] : 0.0f;
    }
    __syncthreads();
    int ln = tid >> 6, c = tid & 63;
    int node = node0 + ln;
    if (node >= n) return;
    float acc = 0.0f;
#pragma unroll
    for (int k = 0; k < 32; k++) acc += hs[ln][k] * Ws[k * 64 + c];
    if (c < HC) g_xl[(size_t)node * HC + c] = acc;
    else        g_xr[(size_t)node * HC + (c - HC)] = acc;
}

// ---------------- layer 2: attention + ELU + FC + log_softmax -> out -----------
__global__ __launch_bounds__(256) void k_attn2(const float* __restrict__ att,
                                               const float* __restrict__ bias,
                                               const float* __restrict__ fcW,
                                               const float* __restrict__ fcb,
                                               float* __restrict__ out, int n)
{
    int w = (blockIdx.x * blockDim.x + threadIdx.x) >> 5;
    int lane = threadIdx.x & 31;
    if (w >= n) return;
    float v = attn_node(w, lane, att, bias);
    float h2 = (v > 0.0f) ? v : expm1f(v);

    float lg[7];
#pragma unroll
    for (int j = 0; j < 7; j++) {
        float p = h2 * fcW[lane * 7 + j];
        p += __shfl_xor_sync(0xffffffffu, p, 16);
        p += __shfl_xor_sync(0xffffffffu, p, 8);
        p += __shfl_xor_sync(0xffffffffu, p, 4);
        p += __shfl_xor_sync(0xffffffffu, p, 2);
        p += __shfl_xor_sync(0xffffffffu, p, 1);
        lg[j] = p + fcb[j];
    }
    if (lane == 0) {
        float mx = lg[0];
#pragma unroll
        for (int j = 1; j < 7; j++) mx = fmaxf(mx, lg[j]);
        float ss = 0.0f;
#pragma unroll
        for (int j = 0; j < 7; j++) ss += expf(lg[j] - mx);
        float lse = mx + logf(ss);
#pragma unroll
        for (int j = 0; j < 7; j++) out[(size_t)w * 7 + j] = lg[j] - lse;
    }
}

// ---------------- launch ---------------------------------------------------------
extern "C" void kernel_launch(void* const* d_in, const int* in_sizes, int n_in,
                              void* d_out, int out_size)
{
    const float* x    = (const float*)d_in[0];
    const void*  ei   = d_in[1];
    const float* Wl1  = (const float*)d_in[2];
    const float* Wr1  = (const float*)d_in[3];
    const float* a1   = (const float*)d_in[4];
    const float* b1   = (const float*)d_in[5];
    const float* Wl2  = (const float*)d_in[6];
    const float* Wr2  = (const float*)d_in[7];
    const float* a2   = (const float*)d_in[8];
    const float* b2   = (const float*)d_in[9];
    const float* fcW  = (const float*)d_in[10];
    const float* fcb  = (const float*)d_in[11];
    float*       out  = (float*)d_out;

    const int K = in_sizes[2] / HC;          // 1433
    const int n = in_sizes[0] / K;           // 100000
    const int E = in_sizes[1] / 2;           // 3200000
    const int etot = E + n;

    const int TB = 256;
    dim3 gEdge((etot + TB - 1) / TB);
    dim3 gN((n + TB - 1) / TB);
    int nWarpBlocks = (n * 32 + TB - 1) / TB;   // one warp per node
    int nb1024 = (n + 1023) / 1024;

    // --- decode + CSR build
    k_flag0<<<1, 32>>>();
    k_detect<<<(E + TB - 1) / TB, TB>>>((const int*)ei, E);
    k_prep<<<gEdge, TB>>>(ei, E, n);
    k_zero<<<gN, TB>>>(n);
    k_hist<<<gEdge, TB>>>(etot);
    k_scan1<<<nb1024, 1024>>>(n);
    k_scan2<<<1, 32>>>(nb1024);
    k_scan3<<<gN, TB>>>(n, etot);
    k_scatter<<<gEdge, TB>>>(etot);

    // --- layer 1
    k_gemm1<<<(n + 127) / 128, 256>>>(x, Wl1, Wr1, n, K);
    k_attn1<<<nWarpBlocks, TB>>>(a1, b1, n);

    // --- layer 2
    k_gemm2<<<(n + 3) / 4, 256>>>(Wl2, Wr2, n);
    k_attn2<<<nWarpBlocks, TB>>>(a2, b2, fcW, fcb, out, n);
}

// round 5
// speedup vs baseline: 1.7195x; 1.0977x over previous
#include <cuda_runtime.h>
#include <math.h>

// ---------------- problem constants ------------------------------------------
#define NMAX   100000
#define EMAX   3200000
#define ETOTMAX (EMAX + NMAX)
#define HC     32          // H*C

// ---------------- scratch (device globals: allocation-free rule) -------------
__device__ __align__(128) float g_xl [NMAX * HC];
__device__ __align__(128) float g_xr [NMAX * HC];
__device__ __align__(128) float g_h  [NMAX * HC];
__device__ __align__(128) int   g_src[ETOTMAX];
__device__ __align__(128) int   g_dst[ETOTMAX];
__device__ __align__(128) int   g_csrc[ETOTMAX];   // CSR: src ids sorted by dst
__device__ __align__(128) int   g_cnt[NMAX];
__device__ __align__(128) int   g_rp [NMAX + 1];   // CSR row pointers
__device__ __align__(128) int   g_pos[NMAX];       // scatter cursors
__device__ int g_i32flag;   // 1 if edge_index delivered as int32, 0 if int64

// ---------------- small PTX helpers ------------------------------------------
__device__ __forceinline__ unsigned long long dup2(float v) {
    unsigned long long r;
    asm("mov.b64 %0, {%1, %1};" : "=l"(r) : "f"(v));
    return r;
}
__device__ __forceinline__ float2 unpack2(unsigned long long v) {
    float2 r;
    asm("mov.b64 {%0, %1}, %2;" : "=f"(r.x), "=f"(r.y) : "l"(v));
    return r;
}
#define FMA2(d, a, b) asm("fma.rn.f32x2 %0, %1, %2, %0;" : "+l"(d) : "l"(a), "l"(b))

// ---------------- dtype detect (int32 vs int64 edge_index) -------------------
__global__ void k_flag0() { if (threadIdx.x == 0 && blockIdx.x == 0) g_i32flag = 0; }

__global__ void k_detect(const int* __restrict__ w, int E) {
    long long i = (long long)blockIdx.x * blockDim.x + threadIdx.x;
    if (i >= E) return;
    if (w[2 * i + 1] != 0) g_i32flag = 1;     // benign race
}

// ---------------- edge decode (+ self loops, clamp) ---------------------------
__global__ void k_prep(const void* __restrict__ eiv, int E, int n) {
    int i = blockIdx.x * blockDim.x + threadIdx.x;
    int etot = E + n;
    if (i >= etot) return;
    int s, d;
    if (i < E) {
        if (g_i32flag) {
            const int* ei = (const int*)eiv;
            s = ei[i]; d = ei[(size_t)E + i];
        } else {
            const long long* ei = (const long long*)eiv;
            s = (int)ei[i]; d = (int)ei[(size_t)E + i];
        }
        s = min(max(s, 0), n - 1);
        d = min(max(d, 0), n - 1);
    } else {
        s = i - E; d = i - E;
    }
    g_src[i] = s;
    g_dst[i] = d;
}

// ---------------- counting sort by dst ----------------------------------------
__global__ void k_zero(int n) {
    int i = blockIdx.x * blockDim.x + threadIdx.x;
    if (i < n) g_cnt[i] = 0;
}
__global__ void k_hist(int etot) {
    int i = blockIdx.x * blockDim.x + threadIdx.x;
    if (i < etot) atomicAdd(&g_cnt[g_dst[i]], 1);
}
__device__ __align__(128) int g_blk[128];
__global__ __launch_bounds__(1024) void k_scan1(int n) {
    __shared__ int sh[1024];
    int i = blockIdx.x * 1024 + threadIdx.x;
    int v = (i < n) ? g_cnt[i] : 0;
    sh[threadIdx.x] = v;
    __syncthreads();
#pragma unroll
    for (int o = 1; o < 1024; o <<= 1) {
        int t = (threadIdx.x >= o) ? sh[threadIdx.x - o] : 0;
        __syncthreads();
        sh[threadIdx.x] += t;
        __syncthreads();
    }
    if (i < n) g_rp[i] = sh[threadIdx.x] - v;   // exclusive
    if (threadIdx.x == 1023) g_blk[blockIdx.x] = sh[1023];
}
__global__ void k_scan2(int nb) {
    if (threadIdx.x == 0 && blockIdx.x == 0) {
        int run = 0;
        for (int b = 0; b < nb; b++) { int t = g_blk[b]; g_blk[b] = run; run += t; }
    }
}
__global__ void k_scan3(int n, int etot) {
    int i = blockIdx.x * blockDim.x + threadIdx.x;
    if (i < n) {
        int v = g_rp[i] + g_blk[i >> 10];
        g_rp[i] = v;
        g_pos[i] = v;
    }
    if (i == 0) g_rp[n] = etot;
}
__global__ void k_scatter(int etot) {
    int i = blockIdx.x * blockDim.x + threadIdx.x;
    if (i >= etot) return;
    int p = atomicAdd(&g_pos[g_dst[i]], 1);
    g_csrc[p] = g_src[i];
}

// ---------------- big fused GEMM  x @ [Wl | Wr] -> xl, xr  (double-buffered) --
__global__ __launch_bounds__(256) void k_gemm1(
    const float* __restrict__ x, const float* __restrict__ Wl,
    const float* __restrict__ Wr, int n, int K)
{
    __shared__ float Xs[2][16][128];
    __shared__ float Ws[2][16][64];

    const int tid = threadIdx.x;
    const int tx = tid & 15, ty = tid >> 4;
    const int row0 = blockIdx.x * 128;
    const int my_r = ty * 8;
    const int my_c = tx * 4;

    unsigned long long acc[4][4];
#pragma unroll
    for (int i = 0; i < 4; i++)
#pragma unroll
        for (int j = 0; j < 4; j++) acc[i][j] = 0ull;

    // load-role addressing (fixed across chunks)
    const int wk = tid >> 4;        // W: k-row within chunk
    const int wc4 = tid & 15;       // W: 4-col group
    const float* wsrc = (wc4 < 8) ? Wl : Wr;
    const int wcc = (wc4 < 8) ? wc4 * 4 : (wc4 - 8) * 4;

    const int xr_  = (tid + 0)   >> 2;     // X: row for slot 0
    const int xr2_ = (tid + 256) >> 2;     // X: row for slot 1
    const int xkq  = (tid & 3) * 4;        // X: k quad
    int gr1 = row0 + xr_;  if (gr1 >= n) gr1 = n - 1;
    int gr2 = row0 + xr2_; if (gr2 >= n) gr2 = n - 1;
    const float* xp1 = x + (size_t)gr1 * K + xkq;
    const float* xp2 = x + (size_t)gr2 * K + xkq;

    const int nch = (K + 15) >> 4;

    float xreg[2][4];
    float4 wreg;

    // ---- prefetch chunk 0
#pragma unroll
    for (int q = 0; q < 4; q++) {
        xreg[0][q] = (xkq + q < K) ? xp1[q] : 0.0f;
        xreg[1][q] = (xkq + q < K) ? xp2[q] : 0.0f;
    }
    wreg = make_float4(0.f, 0.f, 0.f, 0.f);
    if (wk < K) wreg = *(const float4*)(wsrc + (size_t)wk * HC + wcc);

    // ---- store buf 0
#pragma unroll
    for (int q = 0; q < 4; q++) {
        Xs[0][xkq + q][xr_]  = xreg[0][q];
        Xs[0][xkq + q][xr2_] = xreg[1][q];
    }
    *(float4*)&Ws[0][wk][wc4 * 4] = wreg;
    __syncthreads();

    for (int c = 0; c < nch; c++) {
        const int buf = c & 1;
        const int k0n = (c + 1) * 16;
        const bool more = (c + 1 < nch);

        if (more) {
#pragma unroll
            for (int q = 0; q < 4; q++) {
                int gk = k0n + xkq + q;
                xreg[0][q] = (gk < K) ? xp1[k0n + q] : 0.0f;
                xreg[1][q] = (gk < K) ? xp2[k0n + q] : 0.0f;
            }
            wreg = make_float4(0.f, 0.f, 0.f, 0.f);
            int gk = k0n + wk;
            if (gk < K) wreg = *(const float4*)(wsrc + (size_t)gk * HC + wcc);
        }

#pragma unroll
        for (int kk = 0; kk < 16; kk++) {
            ulonglong2 xa = *(const ulonglong2*)&Xs[buf][kk][my_r];
            ulonglong2 xb = *(const ulonglong2*)&Xs[buf][kk][my_r + 4];
            float4 wv = *(const float4*)&Ws[buf][kk][my_c];
            unsigned long long w0 = dup2(wv.x), w1 = dup2(wv.y);
            unsigned long long w2 = dup2(wv.z), w3 = dup2(wv.w);
            FMA2(acc[0][0], xa.x, w0); FMA2(acc[0][1], xa.x, w1);
            FMA2(acc[0][2], xa.x, w2); FMA2(acc[0][3], xa.x, w3);
            FMA2(acc[1][0], xa.y, w0); FMA2(acc[1][1], xa.y, w1);
            FMA2(acc[1][2], xa.y, w2); FMA2(acc[1][3], xa.y, w3);
            FMA2(acc[2][0], xb.x, w0); FMA2(acc[2][1], xb.x, w1);
            FMA2(acc[2][2], xb.x, w2); FMA2(acc[2][3], xb.x, w3);
            FMA2(acc[3][0], xb.y, w0); FMA2(acc[3][1], xb.y, w1);
            FMA2(acc[3][2], xb.y, w2); FMA2(acc[3][3], xb.y, w3);
        }

        if (more) {
            const int nb = buf ^ 1;
#pragma unroll
            for (int q = 0; q < 4; q++) {
                Xs[nb][xkq + q][xr_]  = xreg[0][q];
                Xs[nb][xkq + q][xr2_] = xreg[1][q];
            }
            *(float4*)&Ws[nb][wk][wc4 * 4] = wreg;
        }
        __syncthreads();
    }

    // ---- store results
    float* base = (my_c < HC) ? g_xl : g_xr;
    int cc = my_c & (HC - 1);
#pragma unroll
    for (int rp = 0; rp < 4; rp++) {
        float2 p0 = unpack2(acc[rp][0]);
        float2 p1 = unpack2(acc[rp][1]);
        float2 p2 = unpack2(acc[rp][2]);
        float2 p3 = unpack2(acc[rp][3]);
        int r_even = row0 + my_r + rp * 2;
        if (r_even < n)
            *(float4*)&base[(size_t)r_even * HC + cc] = make_float4(p0.x, p1.x, p2.x, p3.x);
        int r_odd = r_even + 1;
        if (r_odd < n)
            *(float4*)&base[(size_t)r_odd * HC + cc] = make_float4(p0.y, p1.y, p2.y, p3.y);
    }
}

// ---------------- per-node attention core (quad-edge, float4 lanes) ------------
// warp = node; lane = eq*8 + c8 : eq = edge slot (4 edges/step), c8 = channel quad.
// On return: lanes 0..7 hold acc (4 channels each) and ssum for their head.
__device__ __forceinline__ void attn_core(int node, int lane,
                                          const float* __restrict__ att,
                                          float4& accOut, float& ssumOut)
{
    const int c8 = lane & 7;
    const int eq = lane >> 3;
    const int beg = g_rp[node], end = g_rp[node + 1];
    const float4 xr4 = *(const float4*)(g_xr + (size_t)node * HC + c8 * 4);
    const float4 a4  = *(const float4*)(att + c8 * 4);
    float4 acc = make_float4(0.f, 0.f, 0.f, 0.f);
    float ssum = 0.f;

    for (int base = beg; base < end; base += 32) {
        int idx = base + lane;
        int sl = (idx < end) ? g_csrc[idx] : 0;
        int nsteps = min(32, end - base);
        for (int k4 = 0; k4 < nsteps; k4 += 4) {
            int sk = __shfl_sync(0xffffffffu, sl, k4 + eq);
            bool valid = (k4 + eq) < nsteps;
            float4 xl4 = __ldg((const float4*)(g_xl + (size_t)sk * HC) + c8);
            float z, p;
            z = xl4.x + xr4.x; z = fmaxf(z, 0.2f * z); p = z * a4.x;
            z = xl4.y + xr4.y; z = fmaxf(z, 0.2f * z); p = fmaf(z, a4.y, p);
            z = xl4.z + xr4.z; z = fmaxf(z, 0.2f * z); p = fmaf(z, a4.z, p);
            z = xl4.w + xr4.w; z = fmaxf(z, 0.2f * z); p = fmaf(z, a4.w, p);
            p += __shfl_xor_sync(0xffffffffu, p, 1);
            p += __shfl_xor_sync(0xffffffffu, p, 2);   // per-head score (within octet)
            float ex = valid ? __expf(p) : 0.0f;
            ssum += ex;
            acc.x = fmaf(ex, xl4.x, acc.x);
            acc.y = fmaf(ex, xl4.y, acc.y);
            acc.z = fmaf(ex, xl4.z, acc.z);
            acc.w = fmaf(ex, xl4.w, acc.w);
        }
    }
    // combine the 4 edge slots (lanes differing in bits 3,4)
#pragma unroll
    for (int o = 8; o <= 16; o <<= 1) {
        acc.x += __shfl_xor_sync(0xffffffffu, acc.x, o);
        acc.y += __shfl_xor_sync(0xffffffffu, acc.y, o);
        acc.z += __shfl_xor_sync(0xffffffffu, acc.z, o);
        acc.w += __shfl_xor_sync(0xffffffffu, acc.w, o);
        ssum  += __shfl_xor_sync(0xffffffffu, ssum,  o);
    }
    accOut = acc;
    ssumOut = ssum;
}

// ---------------- layer 1: attention + bias + ELU -> g_h ------------------------
__global__ __launch_bounds__(256) void k_attn1(const float* __restrict__ att,
                                               const float* __restrict__ bias, int n)
{
    int w = (blockIdx.x * blockDim.x + threadIdx.x) >> 5;
    int lane = threadIdx.x & 31;
    if (w >= n) return;
    float4 acc; float ssum;
    attn_core(w, lane, att, acc, ssum);
    if (lane < 8) {
        float inv = 1.0f / (ssum + 1e-16f);
        float4 b4 = *(const float4*)(bias + lane * 4);
        float4 o;
        o.x = fmaf(acc.x, inv, b4.x); o.x = (o.x > 0.f) ? o.x : expm1f(o.x);
        o.y = fmaf(acc.y, inv, b4.y); o.y = (o.y > 0.f) ? o.y : expm1f(o.y);
        o.z = fmaf(acc.z, inv, b4.z); o.z = (o.z > 0.f) ? o.z : expm1f(o.z);
        o.w = fmaf(acc.w, inv, b4.w); o.w = (o.w > 0.f) ? o.w : expm1f(o.w);
        *(float4*)(g_h + (size_t)w * HC + lane * 4) = o;
    }
}

// ---------------- small GEMM  h @ [Wl2 | Wr2] (K=32) ----------------------------
__global__ __launch_bounds__(256) void k_gemm2(
    const float* __restrict__ Wl, const float* __restrict__ Wr, int n)
{
    __shared__ float Ws[32 * 64];
    __shared__ float hs[4][32];
    int tid = threadIdx.x;
#pragma unroll
    for (int l = 0; l < 8; l++) {
        int id = tid + l * 256;
        int k = id >> 6, c = id & 63;
        Ws[id] = (c < HC) ? Wl[k * HC + c] : Wr[k * HC + (c - HC)];
    }
    int node0 = blockIdx.x * 4;
    if (tid < 128) {
        int nn = node0 + (tid >> 5), k = tid & 31;
        hs[tid >> 5][k] = (nn < n) ? g_h[(size_t)nn * HC + k] : 0.0f;
    }
    __syncthreads();
    int ln = tid >> 6, c = tid & 63;
    int node = node0 + ln;
    if (node >= n) return;
    float acc = 0.0f;
#pragma unroll
    for (int k = 0; k < 32; k++) acc += hs[ln][k] * Ws[k * 64 + c];
    if (c < HC) g_xl[(size_t)node * HC + c] = acc;
    else        g_xr[(size_t)node * HC + (c - HC)] = acc;
}

// ---------------- layer 2: attention + ELU + FC + log_softmax -> out ------------
__global__ __launch_bounds__(256) void k_attn2(const float* __restrict__ att,
                                               const float* __restrict__ bias,
                                               const float* __restrict__ fcW,
                                               const float* __restrict__ fcb,
                                               float* __restrict__ out, int n)
{
    int w = (blockIdx.x * blockDim.x + threadIdx.x) >> 5;
    int lane = threadIdx.x & 31;
    if (w >= n) return;
    float4 acc; float ssum;
    attn_core(w, lane, att, acc, ssum);

    float4 h2 = make_float4(0.f, 0.f, 0.f, 0.f);
    if (lane < 8) {
        float inv = 1.0f / (ssum + 1e-16f);
        float4 b4 = *(const float4*)(bias + lane * 4);
        h2.x = fmaf(acc.x, inv, b4.x); h2.x = (h2.x > 0.f) ? h2.x : expm1f(h2.x);
        h2.y = fmaf(acc.y, inv, b4.y); h2.y = (h2.y > 0.f) ? h2.y : expm1f(h2.y);
        h2.z = fmaf(acc.z, inv, b4.z); h2.z = (h2.z > 0.f) ? h2.z : expm1f(h2.z);
        h2.w = fmaf(acc.w, inv, b4.w); h2.w = (h2.w > 0.f) ? h2.w : expm1f(h2.w);
    }

    float lg[7];
#pragma unroll
    for (int j = 0; j < 7; j++) {
        float p = 0.0f;
        if (lane < 8) {
            const float* wp = fcW + (lane * 4) * 7 + j;
            p = h2.x * wp[0] + h2.y * wp[7] + h2.z * wp[14] + h2.w * wp[21];
        }
        p += __shfl_xor_sync(0xffffffffu, p, 1);
        p += __shfl_xor_sync(0xffffffffu, p, 2);
        p += __shfl_xor_sync(0xffffffffu, p, 4);
        lg[j] = p;
    }
    if (lane == 0) {
        float mx = -1e30f;
#pragma unroll
        for (int j = 0; j < 7; j++) { lg[j] += fcb[j]; mx = fmaxf(mx, lg[j]); }
        float ss = 0.0f;
#pragma unroll
        for (int j = 0; j < 7; j++) ss += expf(lg[j] - mx);
        float lse = mx + logf(ss);
#pragma unroll
        for (int j = 0; j < 7; j++) out[(size_t)w * 7 + j] = lg[j] - lse;
    }
}

// ---------------- launch ---------------------------------------------------------
extern "C" void kernel_launch(void* const* d_in, const int* in_sizes, int n_in,
                              void* d_out, int out_size)
{
    const float* x    = (const float*)d_in[0];
    const void*  ei   = d_in[1];
    const float* Wl1  = (const float*)d_in[2];
    const float* Wr1  = (const float*)d_in[3];
    const float* a1   = (const float*)d_in[4];
    const float* b1   = (const float*)d_in[5];
    const float* Wl2  = (const float*)d_in[6];
    const float* Wr2  = (const float*)d_in[7];
    const float* a2   = (const float*)d_in[8];
    const float* b2   = (const float*)d_in[9];
    const float* fcW  = (const float*)d_in[10];
    const float* fcb  = (const float*)d_in[11];
    float*       out  = (float*)d_out;

    const int K = in_sizes[2] / HC;          // 1433
    const int n = in_sizes[0] / K;           // 100000
    const int E = in_sizes[1] / 2;           // 3200000
    const int etot = E + n;

    const int TB = 256;
    dim3 gEdge((etot + TB - 1) / TB);
    dim3 gN((n + TB - 1) / TB);
    int nWarpBlocks = (n * 32 + TB - 1) / TB;   // one warp per node
    int nb1024 = (n + 1023) / 1024;

    // --- decode + CSR build
    k_flag0<<<1, 32>>>();
    k_detect<<<(E + TB - 1) / TB, TB>>>((const int*)ei, E);
    k_prep<<<gEdge, TB>>>(ei, E, n);
    k_zero<<<gN, TB>>>(n);
    k_hist<<<gEdge, TB>>>(etot);
    k_scan1<<<nb1024, 1024>>>(n);
    k_scan2<<<1, 32>>>(nb1024);
    k_scan3<<<gN, TB>>>(n, etot);
    k_scatter<<<gEdge, TB>>>(etot);

    // --- layer 1
    k_gemm1<<<(n + 127) / 128, 256>>>(x, Wl1, Wr1, n, K);
    k_attn1<<<nWarpBlocks, TB>>>(a1, b1, n);

    // --- layer 2
    k_gemm2<<<(n + 3) / 4, 256>>>(Wl2, Wr2, n);
    k_attn2<<<nWarpBlocks, TB>>>(a2, b2, fcW, fcb, out, n);
}